// round 1
// baseline (speedup 1.0000x reference)
#include <cuda_runtime.h>
#include <cuda_bf16.h>
#include <cstdint>

#define N_PTS 16384
#define D_DIM 128
#define BM 128
#define BN 128
#define LDS 136              // padded smem row stride (elements) -> conflict-free ldmatrix
#define NTILES (N_PTS / BN)
#define INV_T 14.285714285714286f
#define C1_EXP 20.609929155556625f   // log2(e)/T ; exp((s-1)/T) = 2^(s*C1 - C1)

__device__ __nv_bfloat16 g_Xb[N_PTS * D_DIM];   // 4 MB bf16 copy of x
__device__ float g_rowsum[N_PTS];               // per-row sum of exp((s-1)/T)

// ---------------------------------------------------------------- convert
__global__ void convert_kernel(const float* __restrict__ x) {
    int idx = blockIdx.x * blockDim.x + threadIdx.x;
    const int total = N_PTS * D_DIM / 4;
    if (idx < total) {
        float4 v = ((const float4*)x)[idx];
        __nv_bfloat162 h0, h1;
        h0.x = __float2bfloat16(v.x); h0.y = __float2bfloat16(v.y);
        h1.x = __float2bfloat16(v.z); h1.y = __float2bfloat16(v.w);
        __nv_bfloat162* out = (__nv_bfloat162*)g_Xb;
        out[idx * 2 + 0] = h0;
        out[idx * 2 + 1] = h1;
    }
}

// ---------------------------------------------------------------- helpers
__device__ __forceinline__ uint32_t s2u(const void* p) {
    return (uint32_t)__cvta_generic_to_shared(p);
}
__device__ __forceinline__ void cp16(uint32_t s, const void* g) {
    asm volatile("cp.async.cg.shared.global [%0], [%1], 16;\n" :: "r"(s), "l"(g));
}
__device__ __forceinline__ void ldmx4(uint32_t (&r)[4], uint32_t addr) {
    asm volatile("ldmatrix.sync.aligned.m8n8.x4.shared.b16 {%0,%1,%2,%3}, [%4];\n"
                 : "=r"(r[0]), "=r"(r[1]), "=r"(r[2]), "=r"(r[3]) : "r"(addr));
}
__device__ __forceinline__ void mma16816(float* c, const uint32_t* a, uint32_t b0, uint32_t b1) {
    asm volatile(
        "mma.sync.aligned.m16n8k16.row.col.f32.bf16.bf16.f32 "
        "{%0,%1,%2,%3}, {%4,%5,%6,%7}, {%8,%9}, {%0,%1,%2,%3};\n"
        : "+f"(c[0]), "+f"(c[1]), "+f"(c[2]), "+f"(c[3])
        : "r"(a[0]), "r"(a[1]), "r"(a[2]), "r"(a[3]), "r"(b0), "r"(b1));
}
__device__ __forceinline__ float ex2(float x) {
    float r;
    asm("ex2.approx.f32 %0, %1;" : "=f"(r) : "f"(x));
    return r;
}

// ---------------------------------------------------------------- main GEMM + fused exp-rowsum
// Grid: 128 CTAs, each owns 128 rows (A tile, resident). Loops over all 128
// column tiles of 128 (B tiles, cp.async double-buffered). Accumulators stay
// in registers; exp is applied straight on them (max is known = 1/T since
// rows are L2-normalized -> no online softmax needed).
__global__ void __launch_bounds__(256, 1) gram_lse_kernel() {
    extern __shared__ __nv_bfloat16 smem[];
    __nv_bfloat16* sA  = smem;               // BM x LDS
    __nv_bfloat16* sB0 = smem + BM * LDS;    // BN x LDS
    __nv_bfloat16* sB1 = sB0 + BN * LDS;     // BN x LDS

    const int tid    = threadIdx.x;
    const int lane   = tid & 31;
    const int wid    = tid >> 5;
    const int warp_m = wid & 3;    // 4 warps along M  (warp tile 32 x 64)
    const int warp_n = wid >> 2;   // 2 warps along N
    const int row0   = blockIdx.x * BM;

    // ---- preload A tile (our 128 rows) and B tile 0
    {
        const int r = tid >> 4;          // 0..15
        const int c = (tid & 15) * 8;    // element col, 16B chunks
        #pragma unroll
        for (int p = 0; p < 8; p++) {
            int rr = p * 16 + r;
            cp16(s2u(&sA[rr * LDS + c]), &g_Xb[(row0 + rr) * D_DIM + c]);
        }
        #pragma unroll
        for (int p = 0; p < 8; p++) {
            int rr = p * 16 + r;
            cp16(s2u(&sB0[rr * LDS + c]), &g_Xb[rr * D_DIM + c]);
        }
    }
    asm volatile("cp.async.commit_group;\n");

    float rowpart[4] = {0.f, 0.f, 0.f, 0.f};   // 4 rows owned by this thread

    for (int t = 0; t < NTILES; t++) {
        __nv_bfloat16* sBc = (t & 1) ? sB1 : sB0;
        if (t + 1 < NTILES) {
            __nv_bfloat16* sBn = (t & 1) ? sB0 : sB1;
            const int r = tid >> 4;
            const int c = (tid & 15) * 8;
            #pragma unroll
            for (int p = 0; p < 8; p++) {
                int rr = p * 16 + r;
                cp16(s2u(&sBn[rr * LDS + c]), &g_Xb[((t + 1) * BN + rr) * D_DIM + c]);
            }
            asm volatile("cp.async.commit_group;\n");
            asm volatile("cp.async.wait_group 1;\n");
        } else {
            asm volatile("cp.async.wait_group 0;\n");
        }
        __syncthreads();

        float acc[2][8][4];
        #pragma unroll
        for (int mf = 0; mf < 2; mf++)
            #pragma unroll
            for (int nb = 0; nb < 8; nb++)
                #pragma unroll
                for (int q = 0; q < 4; q++) acc[mf][nb][q] = 0.f;

        #pragma unroll
        for (int kk = 0; kk < 8; kk++) {
            const int acol = kk * 16 + ((lane >> 4) << 3);
            uint32_t a[2][4];
            #pragma unroll
            for (int mf = 0; mf < 2; mf++) {
                int arow = warp_m * 32 + mf * 16 + (lane & 15);
                ldmx4(a[mf], s2u(&sA[arow * LDS + acol]));
            }
            uint32_t bfr[8][2];
            #pragma unroll
            for (int nb = 0; nb < 4; nb++) {
                int brow = warp_n * 64 + nb * 16 + (lane & 15);
                uint32_t r4[4];
                ldmx4(r4, s2u(&sBc[brow * LDS + acol]));
                bfr[nb * 2 + 0][0] = r4[0]; bfr[nb * 2 + 0][1] = r4[2];
                bfr[nb * 2 + 1][0] = r4[1]; bfr[nb * 2 + 1][1] = r4[3];
            }
            #pragma unroll
            for (int mf = 0; mf < 2; mf++)
                #pragma unroll
                for (int nb = 0; nb < 8; nb++)
                    mma16816(acc[mf][nb], a[mf], bfr[nb][0], bfr[nb][1]);
        }

        // fused epilogue: exp((s-1)/T) accumulated per row, straight from registers
        #pragma unroll
        for (int mf = 0; mf < 2; mf++)
            #pragma unroll
            for (int nb = 0; nb < 8; nb++) {
                rowpart[mf * 2 + 0] += ex2(fmaf(acc[mf][nb][0], C1_EXP, -C1_EXP))
                                     + ex2(fmaf(acc[mf][nb][1], C1_EXP, -C1_EXP));
                rowpart[mf * 2 + 1] += ex2(fmaf(acc[mf][nb][2], C1_EXP, -C1_EXP))
                                     + ex2(fmaf(acc[mf][nb][3], C1_EXP, -C1_EXP));
            }
        __syncthreads();   // protect sB buffer reuse next iteration
    }

    // ---- reduce: quad lanes hold different n-columns of the same rows
    #pragma unroll
    for (int k = 0; k < 4; k++) {
        rowpart[k] += __shfl_xor_sync(0xffffffffu, rowpart[k], 1);
        rowpart[k] += __shfl_xor_sync(0xffffffffu, rowpart[k], 2);
    }
    // deterministic cross-warp (warp_n = 0/1) combine via two smem slots
    float* srow = (float*)smem;   // [2][BM], aliases smem (done with tiles)
    __syncthreads();
    if ((lane & 3) == 0) {
        #pragma unroll
        for (int mf = 0; mf < 2; mf++)
            #pragma unroll
            for (int p = 0; p < 2; p++) {
                int r = warp_m * 32 + mf * 16 + p * 8 + (lane >> 2);
                srow[warp_n * BM + r] = rowpart[mf * 2 + p];
            }
    }
    __syncthreads();
    if (tid < BM)
        g_rowsum[row0 + tid] = srow[tid] + srow[BM + tid];
}

// ---------------------------------------------------------------- finalize
__global__ void finalize_kernel(float* __restrict__ out) {
    __shared__ float red[256];
    float s = 0.f;
    for (int i = threadIdx.x; i < N_PTS; i += 256)
        s += __logf(g_rowsum[i]);
    red[threadIdx.x] = s;
    __syncthreads();
    for (int ofs = 128; ofs > 0; ofs >>= 1) {
        if (threadIdx.x < ofs) red[threadIdx.x] += red[threadIdx.x + ofs];
        __syncthreads();
    }
    if (threadIdx.x == 0)
        out[0] = red[0] / (float)N_PTS + INV_T;
}

// ---------------------------------------------------------------- launch
extern "C" void kernel_launch(void* const* d_in, const int* in_sizes, int n_in,
                              void* d_out, int out_size) {
    const float* x = (const float*)d_in[0];
    float* out = (float*)d_out;
    constexpr int SMEM_BYTES = (BM * LDS + 2 * BN * LDS) * (int)sizeof(__nv_bfloat16); // 104448
    cudaFuncSetAttribute(gram_lse_kernel, cudaFuncAttributeMaxDynamicSharedMemorySize, SMEM_BYTES);
    convert_kernel<<<(N_PTS * D_DIM / 4 + 255) / 256, 256>>>(x);
    gram_lse_kernel<<<N_PTS / BM, 256, SMEM_BYTES>>>();
    finalize_kernel<<<1, 256>>>(out);
}

// round 3
// speedup vs baseline: 1.8612x; 1.8612x over previous
#include <cuda_runtime.h>
#include <cuda_fp8.h>
#include <cstdint>

#define N_PTS 16384
#define NBLK  128                       // number of 128-row blocks
#define NTILE 8256                      // NBLK*(NBLK+1)/2 upper-tri tiles
#define C1 20.609929155556625f          // log2(e)/T
#define C2 0.0805075357638931f          // C1/256  (compensates 16x quantization scale)
#define INV_T 14.285714285714286f

__device__ uint8_t g_X8[N_PTS * 128];   // e4m3 of 16*x, row-major 128 B/row
__device__ float   g_n2[N_PTS];         // sum of q^2 per row (= MMA diagonal value)
__device__ float   g_part[N_PTS * NBLK];// per-row partial sums, one slot per tile-col
__device__ float   g_blk[NBLK];

// ---------------------------------------------------------------- helpers
__device__ __forceinline__ uint32_t s2u(const void* p) {
    return (uint32_t)__cvta_generic_to_shared(p);
}
__device__ __forceinline__ void cp16(uint32_t s, const void* g) {
    asm volatile("cp.async.cg.shared.global [%0], [%1], 16;\n" :: "r"(s), "l"(g));
}
__device__ __forceinline__ float ex2(float x) {
    float r; asm("ex2.approx.f32 %0, %1;" : "=f"(r) : "f"(x)); return r;
}
__device__ __forceinline__ uint32_t sw(uint32_t b) {     // SW128 swizzle, 128B rows
    return b ^ ((b >> 3) & 0x70);
}
__device__ __forceinline__ void ldmx4(uint32_t (&r)[4], uint32_t addr) {
    asm volatile("ldmatrix.sync.aligned.m8n8.x4.shared.b16 {%0,%1,%2,%3}, [%4];\n"
                 : "=r"(r[0]), "=r"(r[1]), "=r"(r[2]), "=r"(r[3]) : "r"(addr));
}
__device__ __forceinline__ void qmma(float* c, const uint32_t* a, uint32_t b0, uint32_t b1) {
    asm volatile(
        "mma.sync.aligned.m16n8k32.row.col.f32.e4m3.e4m3.f32 "
        "{%0,%1,%2,%3}, {%4,%5,%6,%7}, {%8,%9}, {%0,%1,%2,%3};\n"
        : "+f"(c[0]), "+f"(c[1]), "+f"(c[2]), "+f"(c[3])
        : "r"(a[0]), "r"(a[1]), "r"(a[2]), "r"(a[3]), "r"(b0), "r"(b1));
}
__device__ __forceinline__ float fp8tof(uint32_t b) {
    __half_raw hr = __nv_cvt_fp8_to_halfraw((__nv_fp8_storage_t)b, __NV_E4M3);
    return __half2float(*(__half*)&hr);
}

// ---------------------------------------------------------------- convert: fp32 -> e4m3(16x), + row n2
__global__ void convert_kernel(const float* __restrict__ x) {
    int gw   = (blockIdx.x * blockDim.x + threadIdx.x) >> 5;  // one warp per row
    int lane = threadIdx.x & 31;
    if (gw >= N_PTS) return;
    float4 v = ((const float4*)(x + gw * 128))[lane];
    uint32_t b0 = __nv_cvt_float_to_fp8(v.x * 16.f, __NV_SATFINITE, __NV_E4M3);
    uint32_t b1 = __nv_cvt_float_to_fp8(v.y * 16.f, __NV_SATFINITE, __NV_E4M3);
    uint32_t b2 = __nv_cvt_float_to_fp8(v.z * 16.f, __NV_SATFINITE, __NV_E4M3);
    uint32_t b3 = __nv_cvt_float_to_fp8(v.w * 16.f, __NV_SATFINITE, __NV_E4M3);
    ((uint32_t*)g_X8)[gw * 32 + lane] = b0 | (b1 << 8) | (b2 << 16) | (b3 << 24);
    float q0 = fp8tof(b0), q1 = fp8tof(b1), q2 = fp8tof(b2), q3 = fp8tof(b3);
    float n2 = q0 * q0 + q1 * q1 + q2 * q2 + q3 * q3;
    #pragma unroll
    for (int ofs = 16; ofs > 0; ofs >>= 1)
        n2 += __shfl_xor_sync(0xffffffffu, n2, ofs);
    if (lane == 0) g_n2[gw] = n2;
}

// ---------------------------------------------------------------- one upper-tri tile per CTA
__global__ void __launch_bounds__(256, 2) tile_kernel() {
    __shared__ uint8_t sA[16384];
    __shared__ uint8_t sB[16384];
    __shared__ float rowred[2][128];
    __shared__ float colred[4][128];

    const int tid  = threadIdx.x;
    const int lane = tid & 31;
    const int wid  = tid >> 5;
    const int wm   = wid & 3;     // 4 warps along M (32 rows each)
    const int wn   = wid >> 2;    // 2 warps along N (64 cols each)

    // decode upper-tri tile index -> (I, J), J >= I
    int u = blockIdx.x;
    int I = (int)floorf(128.5f - sqrtf(128.5f * 128.5f - 2.0f * (float)u));
    if (I < 0) I = 0;
    if (I > 127) I = 127;
    #define OFS(i) ((i) * 128 - (i) * ((i) - 1) / 2)
    while (I < 127 && OFS(I + 1) <= u) I++;
    while (I > 0 && OFS(I) > u) I--;
    const int J = I + (u - OFS(I));
    #undef OFS

    // ---- load A (block I) and B (block J): 16 KB each, SW128 swizzled
    {
        const uint32_t dst = (tid < 128) ? s2u(sA) : s2u(sB);
        const uint8_t* src = &g_X8[(size_t)((tid < 128) ? I : J) * 128 * 128];
        const int ptid = tid & 127;
        #pragma unroll
        for (int i = 0; i < 8; i++) {
            int q = i * 128 + ptid;        // 0..1023 16B-chunks
            int row = q >> 3, c = q & 7;
            uint32_t b = (uint32_t)(row * 128 + c * 16);
            cp16(dst + sw(b), src + row * 128 + c * 16);
        }
    }
    asm volatile("cp.async.commit_group;\n" ::: "memory");
    asm volatile("cp.async.wait_group 0;\n" ::: "memory");
    __syncthreads();

    // ---- MMA: warp tile 32 x 64, K=128 in 4 k32 steps
    float acc[2][8][4];
    #pragma unroll
    for (int mf = 0; mf < 2; mf++)
        #pragma unroll
        for (int nb = 0; nb < 8; nb++)
            #pragma unroll
            for (int q = 0; q < 4; q++) acc[mf][nb][q] = 0.f;

    const uint32_t sAu = s2u(sA), sBu = s2u(sB);
    #pragma unroll
    for (int kk = 0; kk < 4; kk++) {
        const int ab = kk * 32 + ((lane >> 4) << 4);   // byte col within row
        uint32_t a[2][4];
        #pragma unroll
        for (int mf = 0; mf < 2; mf++) {
            int arow = wm * 32 + mf * 16 + (lane & 15);
            ldmx4(a[mf], sAu + sw((uint32_t)(arow * 128 + ab)));
        }
        uint32_t bfr[8][2];
        #pragma unroll
        for (int nb4 = 0; nb4 < 4; nb4++) {
            int brow = wn * 64 + nb4 * 16 + (lane & 15);
            uint32_t r4[4];
            ldmx4(r4, sBu + sw((uint32_t)(brow * 128 + ab)));
            bfr[nb4 * 2 + 0][0] = r4[0]; bfr[nb4 * 2 + 0][1] = r4[2];
            bfr[nb4 * 2 + 1][0] = r4[1]; bfr[nb4 * 2 + 1][1] = r4[3];
        }
        #pragma unroll
        for (int mf = 0; mf < 2; mf++)
            #pragma unroll
            for (int nb = 0; nb < 8; nb++)
                qmma(acc[mf][nb], a[mf], bfr[nb][0], bfr[nb][1]);
    }

    // ---- fused exp + row/col partial sums (exp computed ONCE per element)
    float rowl[2][2] = {{0.f, 0.f}, {0.f, 0.f}};
    float coll[8][2];
    #pragma unroll
    for (int nb = 0; nb < 8; nb++) { coll[nb][0] = 0.f; coll[nb][1] = 0.f; }

    #pragma unroll
    for (int mf = 0; mf < 2; mf++)
        #pragma unroll
        for (int nb = 0; nb < 8; nb++) {
            float e0 = ex2(fmaf(acc[mf][nb][0], C2, -C1));
            float e1 = ex2(fmaf(acc[mf][nb][1], C2, -C1));
            float e2 = ex2(fmaf(acc[mf][nb][2], C2, -C1));
            float e3 = ex2(fmaf(acc[mf][nb][3], C2, -C1));
            rowl[mf][0] += e0 + e1;      // row g   of this mf block
            rowl[mf][1] += e2 + e3;      // row g+8
            coll[nb][0] += e0 + e2;      // col 2t
            coll[nb][1] += e1 + e3;      // col 2t+1
        }

    // row reduce: sum over the 4 lanes of each quad (cols)
    #pragma unroll
    for (int mf = 0; mf < 2; mf++)
        #pragma unroll
        for (int h = 0; h < 2; h++) {
            float v = rowl[mf][h];
            v += __shfl_xor_sync(0xffffffffu, v, 1);
            v += __shfl_xor_sync(0xffffffffu, v, 2);
            if ((lane & 3) == 0)
                rowred[wn][wm * 32 + mf * 16 + h * 8 + (lane >> 2)] = v;
        }
    // col reduce: sum over the 8 row-groups (lane>>2)
    #pragma unroll
    for (int nb = 0; nb < 8; nb++)
        #pragma unroll
        for (int h = 0; h < 2; h++) {
            float v = coll[nb][h];
            v += __shfl_xor_sync(0xffffffffu, v, 4);
            v += __shfl_xor_sync(0xffffffffu, v, 8);
            v += __shfl_xor_sync(0xffffffffu, v, 16);
            if (lane < 4)
                colred[wm][wn * 64 + nb * 8 + 2 * lane + h] = v;
        }
    __syncthreads();

    if (tid < 128) {
        float rs = rowred[0][tid] + rowred[1][tid];
        g_part[(size_t)(I * 128 + tid) * NBLK + J] = rs;
        if (I != J) {
            float cs = (colred[0][tid] + colred[1][tid])
                     + (colred[2][tid] + colred[3][tid]);
            g_part[(size_t)(J * 128 + tid) * NBLK + I] = cs;
        }
    }
}

// ---------------------------------------------------------------- reduce rows -> per-block log-sums
__global__ void reduce_kernel() {
    __shared__ float red[128];
    const int i = blockIdx.x * 128 + threadIdx.x;
    const float* p = &g_part[(size_t)i * NBLK];
    float s = 0.f;
    #pragma unroll 8
    for (int j = 0; j < NBLK; j++) s += p[j];
    // replace quantized diagonal term with the exact exp(0)=1
    s += 1.0f - ex2(fmaf(g_n2[i], C2, -C1));
    red[threadIdx.x] = __logf(s);
    __syncthreads();
    for (int ofs = 64; ofs > 0; ofs >>= 1) {
        if (threadIdx.x < ofs) red[threadIdx.x] += red[threadIdx.x + ofs];
        __syncthreads();
    }
    if (threadIdx.x == 0) g_blk[blockIdx.x] = red[0];
}

__global__ void final_kernel(float* __restrict__ out) {
    __shared__ float red[128];
    red[threadIdx.x] = g_blk[threadIdx.x];
    __syncthreads();
    for (int ofs = 64; ofs > 0; ofs >>= 1) {
        if (threadIdx.x < ofs) red[threadIdx.x] += red[threadIdx.x + ofs];
        __syncthreads();
    }
    if (threadIdx.x == 0)
        out[0] = red[0] / (float)N_PTS + INV_T;
}

// ---------------------------------------------------------------- launch
extern "C" void kernel_launch(void* const* d_in, const int* in_sizes, int n_in,
                              void* d_out, int out_size) {
    const float* x = (const float*)d_in[0];
    float* out = (float*)d_out;
    convert_kernel<<<(N_PTS * 32 + 255) / 256, 256>>>(x);
    tile_kernel<<<NTILE, 256>>>();
    reduce_kernel<<<NBLK, 128>>>();
    final_kernel<<<1, 128>>>(out);
}

// round 5
// speedup vs baseline: 1.8887x; 1.0147x over previous
#include <cuda_runtime.h>
#include <cuda_fp8.h>
#include <cstdint>

#define N_PTS 16384
#define NBLK  128                       // number of 128-row blocks
#define NTILE 8256                      // NBLK*(NBLK+1)/2 upper-tri tiles
#define C1 20.609929155556625f          // log2(e)/T
#define C2 0.0805075357638931f          // C1/256  (compensates 16x quantization scale)
#define INV_T 14.285714285714286f

__device__ uint8_t g_X8[N_PTS * 128];   // e4m3 of 16*x, row-major 128 B/row
__device__ float   g_n2[N_PTS];         // sum of q^2 per row (= MMA diagonal value)
__device__ float   g_part[N_PTS * NBLK];// per-row partial sums, one slot per tile-col
__device__ float   g_blk[NBLK];

// ---------------------------------------------------------------- helpers
__device__ __forceinline__ uint32_t s2u(const void* p) {
    return (uint32_t)__cvta_generic_to_shared(p);
}
__device__ __forceinline__ void cp16(uint32_t s, const void* g) {
    asm volatile("cp.async.cg.shared.global [%0], [%1], 16;\n" :: "r"(s), "l"(g));
}
__device__ __forceinline__ float ex2(float x) {
    float r; asm("ex2.approx.f32 %0, %1;" : "=f"(r) : "f"(x)); return r;
}
__device__ __forceinline__ uint32_t sw(uint32_t b) {     // SW128 swizzle, 128B rows
    return b ^ ((b >> 3) & 0x70);
}
__device__ __forceinline__ void ldmx4(uint32_t (&r)[4], uint32_t addr) {
    asm volatile("ldmatrix.sync.aligned.m8n8.x4.shared.b16 {%0,%1,%2,%3}, [%4];\n"
                 : "=r"(r[0]), "=r"(r[1]), "=r"(r[2]), "=r"(r[3]) : "r"(addr));
}
__device__ __forceinline__ void qmma(float* c, const uint32_t* a, uint32_t b0, uint32_t b1) {
    asm volatile(
        "mma.sync.aligned.m16n8k32.row.col.f32.e4m3.e4m3.f32 "
        "{%0,%1,%2,%3}, {%4,%5,%6,%7}, {%8,%9}, {%0,%1,%2,%3};\n"
        : "+f"(c[0]), "+f"(c[1]), "+f"(c[2]), "+f"(c[3])
        : "r"(a[0]), "r"(a[1]), "r"(a[2]), "r"(a[3]), "r"(b0), "r"(b1));
}
__device__ __forceinline__ float fp8tof(uint32_t b) {
    __half_raw hr = __nv_cvt_fp8_to_halfraw((__nv_fp8_storage_t)b, __NV_E4M3);
    return __half2float(*(__half*)&hr);
}

// ---------------------------------------------------------------- convert: fp32 -> e4m3(16x), + row n2
__global__ void convert_kernel(const float* __restrict__ x) {
    int gw   = (blockIdx.x * blockDim.x + threadIdx.x) >> 5;  // one warp per row
    int lane = threadIdx.x & 31;
    if (gw >= N_PTS) return;
    float4 v = ((const float4*)(x + gw * 128))[lane];
    uint32_t b0 = __nv_cvt_float_to_fp8(v.x * 16.f, __NV_SATFINITE, __NV_E4M3);
    uint32_t b1 = __nv_cvt_float_to_fp8(v.y * 16.f, __NV_SATFINITE, __NV_E4M3);
    uint32_t b2 = __nv_cvt_float_to_fp8(v.z * 16.f, __NV_SATFINITE, __NV_E4M3);
    uint32_t b3 = __nv_cvt_float_to_fp8(v.w * 16.f, __NV_SATFINITE, __NV_E4M3);
    ((uint32_t*)g_X8)[gw * 32 + lane] = b0 | (b1 << 8) | (b2 << 16) | (b3 << 24);
    float q0 = fp8tof(b0), q1 = fp8tof(b1), q2 = fp8tof(b2), q3 = fp8tof(b3);
    float n2 = q0 * q0 + q1 * q1 + q2 * q2 + q3 * q3;
    #pragma unroll
    for (int ofs = 16; ofs > 0; ofs >>= 1)
        n2 += __shfl_xor_sync(0xffffffffu, n2, ofs);
    if (lane == 0) g_n2[gw] = n2;
}

// ---------------------------------------------------------------- one upper-tri tile per CTA
__global__ void __launch_bounds__(256, 2) tile_kernel() {
    __shared__ uint8_t sA[16384];
    __shared__ uint8_t sB[16384];
    __shared__ float rowred[2][128];
    __shared__ float colred[4][128];

    const int tid  = threadIdx.x;
    const int lane = tid & 31;
    const int wid  = tid >> 5;
    const int wm   = wid & 3;     // 4 warps along M (32 rows each)
    const int wn   = wid >> 2;    // 2 warps along N (64 cols each)

    // decode upper-tri tile index -> (I, J), J >= I
    int u = blockIdx.x;
    int I = (int)floorf(128.5f - sqrtf(128.5f * 128.5f - 2.0f * (float)u));
    if (I < 0) I = 0;
    if (I > 127) I = 127;
    #define OFS(i) ((i) * 128 - (i) * ((i) - 1) / 2)
    while (I < 127 && OFS(I + 1) <= u) I++;
    while (I > 0 && OFS(I) > u) I--;
    const int J = I + (u - OFS(I));
    #undef OFS

    // ---- load A (block I) and B (block J): 16 KB each, SW128 swizzled
    {
        const uint32_t dst = (tid < 128) ? s2u(sA) : s2u(sB);
        const uint8_t* src = &g_X8[(size_t)((tid < 128) ? I : J) * 128 * 128];
        const int ptid = tid & 127;
        #pragma unroll
        for (int i = 0; i < 8; i++) {
            int q = i * 128 + ptid;        // 0..1023 16B-chunks
            int row = q >> 3, c = q & 7;
            uint32_t b = (uint32_t)(row * 128 + c * 16);
            cp16(dst + sw(b), src + row * 128 + c * 16);
        }
    }
    asm volatile("cp.async.commit_group;\n" ::: "memory");
    asm volatile("cp.async.wait_group 0;\n" ::: "memory");
    __syncthreads();

    const uint32_t sAu = s2u(sA), sBu = s2u(sB);

    // per-thread running sums
    float rowl[2][2] = {{0.f, 0.f}, {0.f, 0.f}};
    float coll[8][2];
    #pragma unroll
    for (int nb = 0; nb < 8; nb++) { coll[nb][0] = 0.f; coll[nb][1] = 0.f; }

    // ---- software-pipelined quarters: 32x16 each, double-buffered accs.
    // mma(q) issued, then epilogue(q-1) runs while HMMA drains (indep regs).
    float acc[2][2][2][4];   // [buf][mf][nbq][4]

    #define MMA_QUARTER(qq, buf) do {                                               \
        _Pragma("unroll")                                                           \
        for (int mf = 0; mf < 2; mf++)                                              \
            _Pragma("unroll")                                                       \
            for (int nq = 0; nq < 2; nq++)                                          \
                _Pragma("unroll")                                                   \
                for (int e = 0; e < 4; e++) acc[buf][mf][nq][e] = 0.f;              \
        _Pragma("unroll")                                                           \
        for (int kk = 0; kk < 4; kk++) {                                            \
            const int ab = kk * 32 + ((lane >> 4) << 4);                            \
            uint32_t a0[4], a1[4], r4[4];                                           \
            ldmx4(a0, sAu + sw((uint32_t)((wm * 32 + (lane & 15)) * 128 + ab)));    \
            ldmx4(a1, sAu + sw((uint32_t)((wm * 32 + 16 + (lane & 15)) * 128 + ab)));\
            ldmx4(r4, sBu + sw((uint32_t)((wn * 64 + (qq) * 16 + (lane & 15)) * 128 + ab)));\
            qmma(acc[buf][0][0], a0, r4[0], r4[2]);                                 \
            qmma(acc[buf][0][1], a0, r4[1], r4[3]);                                 \
            qmma(acc[buf][1][0], a1, r4[0], r4[2]);                                 \
            qmma(acc[buf][1][1], a1, r4[1], r4[3]);                                 \
        }                                                                           \
    } while (0)

    #define EPILOGUE(qq, buf) do {                                                  \
        _Pragma("unroll")                                                           \
        for (int mf = 0; mf < 2; mf++)                                              \
            _Pragma("unroll")                                                       \
            for (int nq = 0; nq < 2; nq++) {                                        \
                const int nb = (qq) * 2 + nq;                                       \
                float e0 = ex2(fmaf(acc[buf][mf][nq][0], C2, -C1));                 \
                float e1 = ex2(fmaf(acc[buf][mf][nq][1], C2, -C1));                 \
                float e2 = ex2(fmaf(acc[buf][mf][nq][2], C2, -C1));                 \
                float e3 = ex2(fmaf(acc[buf][mf][nq][3], C2, -C1));                 \
                rowl[mf][0] += e0 + e1;                                             \
                rowl[mf][1] += e2 + e3;                                             \
                coll[nb][0] += e0 + e2;                                             \
                coll[nb][1] += e1 + e3;                                             \
            }                                                                       \
    } while (0)

    MMA_QUARTER(0, 0);
    MMA_QUARTER(1, 1);
    EPILOGUE(0, 0);
    MMA_QUARTER(2, 0);
    EPILOGUE(1, 1);
    MMA_QUARTER(3, 1);
    EPILOGUE(2, 0);
    EPILOGUE(3, 1);

    #undef MMA_QUARTER
    #undef EPILOGUE

    // row reduce: sum over the 4 lanes of each quad (cols)
    #pragma unroll
    for (int mf = 0; mf < 2; mf++)
        #pragma unroll
        for (int h = 0; h < 2; h++) {
            float v = rowl[mf][h];
            v += __shfl_xor_sync(0xffffffffu, v, 1);
            v += __shfl_xor_sync(0xffffffffu, v, 2);
            if ((lane & 3) == 0)
                rowred[wn][wm * 32 + mf * 16 + h * 8 + (lane >> 2)] = v;
        }
    // col reduce: sum over the 8 row-groups (lane>>2)
    #pragma unroll
    for (int nb = 0; nb < 8; nb++)
        #pragma unroll
        for (int h = 0; h < 2; h++) {
            float v = coll[nb][h];
            v += __shfl_xor_sync(0xffffffffu, v, 4);
            v += __shfl_xor_sync(0xffffffffu, v, 8);
            v += __shfl_xor_sync(0xffffffffu, v, 16);
            if (lane < 4)
                colred[wm][wn * 64 + nb * 8 + 2 * lane + h] = v;
        }
    __syncthreads();

    if (tid < 128) {
        float rs = rowred[0][tid] + rowred[1][tid];
        g_part[(size_t)(I * 128 + tid) * NBLK + J] = rs;
        if (I != J) {
            float cs = (colred[0][tid] + colred[1][tid])
                     + (colred[2][tid] + colred[3][tid]);
            g_part[(size_t)(J * 128 + tid) * NBLK + I] = cs;
        }
    }
}

// ---------------------------------------------------------------- reduce rows -> per-block log-sums
__global__ void reduce_kernel() {
    __shared__ float red[128];
    const int i = blockIdx.x * 128 + threadIdx.x;
    const float* p = &g_part[(size_t)i * NBLK];
    float s = 0.f;
    #pragma unroll 8
    for (int j = 0; j < NBLK; j++) s += p[j];
    // replace quantized diagonal term with the exact exp(0)=1
    s += 1.0f - ex2(fmaf(g_n2[i], C2, -C1));
    red[threadIdx.x] = __logf(s);
    __syncthreads();
    for (int ofs = 64; ofs > 0; ofs >>= 1) {
        if (threadIdx.x < ofs) red[threadIdx.x] += red[threadIdx.x + ofs];
        __syncthreads();
    }
    if (threadIdx.x == 0) g_blk[blockIdx.x] = red[0];
}

__global__ void final_kernel(float* __restrict__ out) {
    __shared__ float red[128];
    red[threadIdx.x] = g_blk[threadIdx.x];
    __syncthreads();
    for (int ofs = 64; ofs > 0; ofs >>= 1) {
        if (threadIdx.x < ofs) red[threadIdx.x] += red[threadIdx.x + ofs];
        __syncthreads();
    }
    if (threadIdx.x == 0)
        out[0] = red[0] / (float)N_PTS + INV_T;
}

// ---------------------------------------------------------------- launch
extern "C" void kernel_launch(void* const* d_in, const int* in_sizes, int n_in,
                              void* d_out, int out_size) {
    const float* x = (const float*)d_in[0];
    float* out = (float*)d_out;
    convert_kernel<<<(N_PTS * 32 + 255) / 256, 256>>>(x);
    tile_kernel<<<NTILE, 256>>>();
    reduce_kernel<<<NBLK, 128>>>();
    final_kernel<<<1, 128>>>(out);
}